// round 7
// baseline (speedup 1.0000x reference)
#include <cuda_runtime.h>

#define NB 64
#define NN 1024
#define NWORDS 32          // NN/32 bitmask words per node row
#define NITER 5
#define MASKW 32768        // words per graph mask (NN*NN/32)

// scratch (no allocations allowed)
__device__ unsigned g_mask[NB * MASKW];  // 8.4MB adjacency bitmasks
__device__ float g_feats[NB * NN];       // per-graph label histograms
__device__ float g_dnorm[NB];            // sqrt(dot(feats_b, feats_b))

// compare-exchange
__device__ __forceinline__ unsigned cex(unsigned a, unsigned b, bool keep_min)
{
    unsigned mn = a < b ? a : b;
    unsigned mx = a < b ? b : a;
    return keep_min ? mn : mx;
}

__device__ __forceinline__ unsigned stage_single(const unsigned* in, int t, int k, int j)
{
    bool asc = ((t & k) == 0);
    return cex(in[t], in[t ^ j], (((t & j) == 0) == asc));
}

// two consecutive stages (j1 then j2=j1/2) fused: 4 reads, 3 cex.
__device__ __forceinline__ unsigned stage_pair(const unsigned* in, int t, int k, int j1, int j2)
{
    bool asc = ((t & k) == 0);
    unsigned x0 = in[t];
    unsigned x1 = in[t ^ j1];
    unsigned y0 = in[t ^ j2];
    unsigned y1 = in[(t ^ j2) ^ j1];
    bool km1 = (((t & j1) == 0) == asc);
    unsigned a  = cex(x0, x1, km1);
    unsigned bb = cex(y0, y1, km1);
    return cex(a, bb, (((t & j2) == 0) == asc));
}

// intra-warp bitonic merge on 32-bit keys: j = jstart..1 via shuffles
__device__ __forceinline__ unsigned warp_merge32(unsigned v, int t, int k, int jstart)
{
    bool dir = ((t & k) == 0);
    #pragma unroll
    for (int j = jstart; j > 0; j >>= 1) {
        unsigned o = __shfl_xor_sync(0xffffffffu, v, j);
        bool keep_min = (((t & j) == 0) == dir);
        unsigned mn = v < o ? v : o;
        unsigned mx = v < o ? o : v;
        v = keep_min ? mn : mx;
    }
    return v;
}

// -------------------------------------------------------------------------
// Kernel 0: zero the global adjacency masks (graph-replayed each call).
// -------------------------------------------------------------------------
extern "C" __global__ void __launch_bounds__(256)
zero_kernel()
{
    uint4* p = (uint4*)g_mask;
    const int n = NB * MASKW / 4;
    for (int i = blockIdx.x * 256 + threadIdx.x; i < n; i += gridDim.x * 256)
        p[i] = make_uint4(0u, 0u, 0u, 0u);
}

// -------------------------------------------------------------------------
// Kernel E: scatter edges into the global masks. One edge per thread,
// spread across the whole chip (RED.OR to L2, no SMEM-atomic serialization).
// -------------------------------------------------------------------------
extern "C" __global__ void __launch_bounds__(256)
edge_kernel(const int* __restrict__ esrc, const int* __restrict__ edst, int E)
{
    const int e = blockIdx.x * 256 + threadIdx.x;
    const int b = blockIdx.y;
    if (e < E) {
        int s = esrc[(size_t)b * E + e];
        int d = edst[(size_t)b * E + e];
        atomicOr(&g_mask[b * MASKW + (s << 5) + (d >> 5)], 1u << (d & 31));
    }
}

// -------------------------------------------------------------------------
// Kernel 1: one block per graph.
// Phase A: coalesced copy of prebuilt mask gmem->SMEM, deg, K, CSR lists.
// Phase B (x5): seg gather -> hash -> hybrid bitonic -> flag-scan ranks
//               -> binary-search rank lookup -> atomic-free histogram.
// Dynamic SMEM (217088 B, opt-in):
//   [0      , 131072) : unsigned smask[32768]   adjacency bits
//   [131072 , 196608) : u16 s_ent[32768]        CSR entries (even-aligned runs)
//   [196608 , 200704) : int s_lab[1024]         labels
//   [200704 , 204800) : int s_cnt[1024]         histogram counts
//   [204800 , 208896) : unsigned s_keyA[1024]   sort ping buffer
//   [208896 , 212992) : unsigned s_keyB[1024]   sort pong buffer (also run-pos)
//   [212992 , 217088) : int s_scan[1024]        rank per sorted position
// -------------------------------------------------------------------------
extern "C" __global__ void __launch_bounds__(1024, 1)
wl_kernel(const int* __restrict__ labels0, const float* __restrict__ hw)
{
    extern __shared__ unsigned char s_raw[];
    unsigned*       smask  = (unsigned*)s_raw;                  // 128KB
    unsigned short* s_ent  = (unsigned short*)(s_raw + 131072); // 64KB
    int*            s_lab  = (int*)(s_raw + 196608);            // 4KB
    int*            s_cnt  = (int*)(s_raw + 200704);            // 4KB
    unsigned*       s_keyA = (unsigned*)(s_raw + 204800);       // 4KB
    unsigned*       s_keyB = (unsigned*)(s_raw + 208896);       // 4KB
    int*            s_scan = (int*)(s_raw + 212992);            // 4KB
    __shared__ int s_warp[32];

    const int t    = threadIdx.x;
    const int b    = blockIdx.x;
    const int lane = t & 31;
    const int wid  = t >> 5;
    const float w0 = hw[0], w1 = hw[1];

    // --- coalesced mask copy gmem -> SMEM (no atomics in this kernel) ---
    {
        const uint4* gm4 = (const uint4*)(g_mask + (size_t)b * MASKW);
        uint4* sm4 = (uint4*)smask;
        #pragma unroll
        for (int i = 0; i < 8; i++) sm4[t + i * 1024] = gm4[t + i * 1024];
    }
    s_cnt[t] = 0;

    // --- initial labels + histogram stage 0 ---
    int mylab = labels0[b * NN + t];
    s_lab[t] = mylab;
    __syncthreads();
    atomicAdd(&s_cnt[mylab], 1);

    // --- degree (staggered word order -> conflict-free LDS) ---
    int deg = 0;
    #pragma unroll
    for (int wi = 0; wi < NWORDS; wi++) {
        int w = (wi + t) & 31;
        deg += __popc(smask[(t << 5) + w]);
    }
    const int degPad = (deg + 1) & ~1;     // even-align each node's CSR run

    // --- K = max degree, exclusive scan of degPad -> even CSR offsets ---
    int kv = deg;
    #pragma unroll
    for (int o = 16; o > 0; o >>= 1) kv = max(kv, __shfl_xor_sync(0xffffffffu, kv, o));
    int incl = degPad;
    #pragma unroll
    for (int o = 1; o < 32; o <<= 1) {
        int n = __shfl_up_sync(0xffffffffu, incl, o);
        if (lane >= o) incl += n;
    }
    if (lane == 31) { s_warp[wid] = incl; s_scan[wid] = kv; }
    __syncthreads();
    if (t < 32) {
        int x = s_warp[t];
        #pragma unroll
        for (int o = 1; o < 32; o <<= 1) {
            int n = __shfl_up_sync(0xffffffffu, x, o);
            if (t >= o) x += n;
        }
        s_warp[t] = x;
        int m = s_scan[t];
        #pragma unroll
        for (int o = 16; o > 0; o >>= 1) m = max(m, __shfl_xor_sync(0xffffffffu, m, o));
        if (t == 0) s_scan[0] = m;
    }
    __syncthreads();
    const int K   = s_scan[0];
    const int off = (wid > 0 ? s_warp[wid - 1] : 0) + incl - degPad;  // even
    __syncthreads();

    // --- build CSR u16 neighbor entries (once) ---
    {
        int p = off;
        #pragma unroll
        for (int w = 0; w < NWORDS; w++) {
            unsigned m = smask[(t << 5) + w];
            int base = w << 5;
            while (m) {
                int bb = __ffs(m) - 1;
                m &= m - 1;
                s_ent[p++] = (unsigned short)(base + bb);
            }
        }
    }
    __syncthreads();

    const float Kw0 = __fmul_rn((float)K, w0);
    const unsigned* e32base = (const unsigned*)s_ent;

    for (int it = 0; it < NITER; it++) {
        // --- seg = sum of neighbor labels; u32-packed reads ---
        int seg = 0;
        {
            const unsigned* e32 = e32base + (off >> 1);
            const int nf = deg >> 1;
            #pragma unroll 4
            for (int n = 0; n < nf; n++) {
                unsigned e = e32[n];
                seg += s_lab[e & 0xFFFFu] + s_lab[e >> 16];
            }
            if (deg & 1) seg += s_lab[s_ent[off + deg - 1]];
        }

        // --- hashed = (K*w0)*lab + w1*(seg+deg-K), no FMA contraction ---
        float h = __fadd_rn(__fmul_rn(Kw0, (float)mylab),
                            __fmul_rn(w1, (float)(seg + deg - K)));
        h = __fadd_rn(h, 0.0f);               // canonicalize -0 -> +0
        unsigned u = __float_as_uint(h);
        u = (u & 0x80000000u) ? ~u : (u | 0x80000000u);   // order-preserving map
        const unsigned mykey = u;
        unsigned v = u;

        // --- warp phase: k = 2..32 in registers ---
        #pragma unroll
        for (int k = 2; k <= 32; k <<= 1)
            v = warp_merge32(v, t, k, k >> 1);

        unsigned* cur = s_keyA;
        unsigned* nxt = s_keyB;
        cur[t] = v;
        __syncthreads();

        // --- k=64 ---
        v = stage_single(cur, t, 64, 32);
        v = warp_merge32(v, t, 64, 16);
        nxt[t] = v; { unsigned* tmp = cur; cur = nxt; nxt = tmp; }
        __syncthreads();

        // --- k=128 ---
        v = stage_pair(cur, t, 128, 64, 32);
        v = warp_merge32(v, t, 128, 16);
        nxt[t] = v; { unsigned* tmp = cur; cur = nxt; nxt = tmp; }
        __syncthreads();

        // --- k=256 ---
        v = stage_pair(cur, t, 256, 128, 64);
        nxt[t] = v; { unsigned* tmp = cur; cur = nxt; nxt = tmp; }
        __syncthreads();
        v = stage_single(cur, t, 256, 32);
        v = warp_merge32(v, t, 256, 16);
        nxt[t] = v; { unsigned* tmp = cur; cur = nxt; nxt = tmp; }
        __syncthreads();

        // --- k=512 ---
        v = stage_pair(cur, t, 512, 256, 128);
        nxt[t] = v; { unsigned* tmp = cur; cur = nxt; nxt = tmp; }
        __syncthreads();
        v = stage_pair(cur, t, 512, 64, 32);
        v = warp_merge32(v, t, 512, 16);
        nxt[t] = v; { unsigned* tmp = cur; cur = nxt; nxt = tmp; }
        __syncthreads();

        // --- k=1024 ---
        v = stage_pair(cur, t, 1024, 512, 256);
        nxt[t] = v; { unsigned* tmp = cur; cur = nxt; nxt = tmp; }
        __syncthreads();
        v = stage_pair(cur, t, 1024, 128, 64);
        nxt[t] = v; { unsigned* tmp = cur; cur = nxt; nxt = tmp; }
        __syncthreads();
        v = stage_single(cur, t, 1024, 32);
        v = warp_merge32(v, t, 1024, 16);
        nxt[t] = v; { unsigned* tmp = cur; cur = nxt; nxt = tmp; }
        __syncthreads();
        // cur[] fully sorted; nxt[] free; v = cur[t]

        // --- rank per sorted position: boundary flag + block scan ---
        int flag = 0;
        if (t > 0) flag = (v != cur[t - 1]) ? 1 : 0;
        int val = flag;
        #pragma unroll
        for (int o = 1; o < 32; o <<= 1) {
            int n = __shfl_up_sync(0xffffffffu, val, o);
            if (lane >= o) val += n;
        }
        if (lane == 31) s_warp[wid] = val;
        __syncthreads();
        if (t < 32) {
            int x = s_warp[t];
            #pragma unroll
            for (int o = 1; o < 32; o <<= 1) {
                int n = __shfl_up_sync(0xffffffffu, x, o);
                if (t >= o) x += n;
            }
            s_warp[t] = x;
        }
        __syncthreads();
        const int rank_p = val + (wid > 0 ? s_warp[wid - 1] : 0);
        int* s_pos = (int*)nxt;           // reuse free pong buffer
        s_scan[t] = rank_p;
        s_pos[t]  = 1024;                 // sentinel
        __syncthreads();

        const bool isstart = (t == 0) | (flag != 0);
        if (isstart) s_pos[rank_p] = t;
        __syncthreads();

        // --- atomic-free histogram: run-length = next start - my start ---
        if (isstart) {
            int end = (rank_p == 1023) ? 1024 : s_pos[rank_p + 1];
            s_cnt[rank_p] += end - t;
        }

        // --- binary-search my key (pow-2 lower_bound, barrier-free) ---
        int lo = 0;
        #pragma unroll
        for (int s = 512; s > 0; s >>= 1)
            if (cur[lo + s - 1] < mykey) lo += s;

        int rank = s_scan[lo];
        s_lab[t] = rank;
        mylab    = rank;
        __syncthreads();
    }

    // --- feats + norm ---
    float c = (float)s_cnt[t];
    g_feats[b * NN + t] = c;

    float sq = c * c;
    #pragma unroll
    for (int o = 16; o > 0; o >>= 1) sq += __shfl_xor_sync(0xffffffffu, sq, o);
    if (lane == 0) s_warp[wid] = __float_as_int(sq);
    __syncthreads();
    if (t < 32) {
        float x = __int_as_float(s_warp[t]);
        #pragma unroll
        for (int o = 16; o > 0; o >>= 1) x += __shfl_xor_sync(0xffffffffu, x, o);
        if (t == 0) g_dnorm[b] = sqrtf(x);
    }
}

// -------------------------------------------------------------------------
// Kernel 2: normalized Gram (round-5 measured-best shape). Grid (64, 2) x
// 1024 threads: warp w of block (b, jt) computes out[b][jt*32+w].
// -------------------------------------------------------------------------
extern "C" __global__ void __launch_bounds__(1024)
gram_kernel(float* __restrict__ out)
{
    __shared__ float sf[NN];
    const int b  = blockIdx.x;
    const int jt = blockIdx.y;
    const int t  = threadIdx.x;
    sf[t] = g_feats[b * NN + t];
    __syncthreads();

    const int warp = t >> 5, lane = t & 31;
    const int j = jt * 32 + warp;
    const float4* sf4 = (const float4*)sf;
    const float4* fj4 = (const float4*)&g_feats[j * NN];
    float s = 0.0f;
    #pragma unroll
    for (int k = lane; k < NN / 4; k += 32) {
        float4 a = sf4[k];
        float4 c = fj4[k];
        s += a.x * c.x + a.y * c.y + a.z * c.z + a.w * c.w;
    }
    #pragma unroll
    for (int o = 16; o > 0; o >>= 1) s += __shfl_xor_sync(0xffffffffu, s, o);
    if (lane == 0) out[b * NB + j] = s / (g_dnorm[b] * g_dnorm[j]);
}

extern "C" void kernel_launch(void* const* d_in, const int* in_sizes, int n_in,
                              void* d_out, int out_size)
{
    const int*   esrc = (const int*)d_in[0];
    const int*   edst = (const int*)d_in[1];
    const int*   lab  = (const int*)d_in[2];
    const float* hw   = (const float*)d_in[3];
    const int E = in_sizes[0] / NB;

    const size_t smem_wl = 217088;  // 128K mask + 64K ent + 5x4K arrays
    static bool attr_done = false;
    if (!attr_done) {
        cudaFuncSetAttribute(wl_kernel, cudaFuncAttributeMaxDynamicSharedMemorySize,
                             (int)smem_wl);
        attr_done = true;
    }
    zero_kernel<<<1024, 256>>>();
    edge_kernel<<<dim3((E + 255) / 256, NB), 256>>>(esrc, edst, E);
    wl_kernel<<<NB, 1024, smem_wl>>>(lab, hw);
    gram_kernel<<<dim3(NB, 2), 1024>>>((float*)d_out);
}

// round 8
// speedup vs baseline: 1.0610x; 1.0610x over previous
#include <cuda_runtime.h>

#define NB 64
#define NN 1024
#define NWORDS 32          // NN/32 bitmask words per node row
#define NITER 5

// scratch (no allocations allowed)
__device__ float g_feats[NB * NN];   // per-graph label histograms (6 stages)
__device__ float g_dnorm[NB];        // sqrt(dot(feats_b, feats_b))

// compare-exchange
__device__ __forceinline__ unsigned cex(unsigned a, unsigned b, bool keep_min)
{
    unsigned mn = a < b ? a : b;
    unsigned mx = a < b ? b : a;
    return keep_min ? mn : mx;
}

__device__ __forceinline__ unsigned stage_single(const unsigned* in, int t, int k, int j)
{
    bool asc = ((t & k) == 0);
    return cex(in[t], in[t ^ j], (((t & j) == 0) == asc));
}

// two consecutive stages (j1 then j2=j1/2) fused: 4 reads, 3 cex.
__device__ __forceinline__ unsigned stage_pair(const unsigned* in, int t, int k, int j1, int j2)
{
    bool asc = ((t & k) == 0);
    bool km1 = (((t & j1) == 0) == asc);
    unsigned a  = cex(in[t],      in[t ^ j1],        km1);
    unsigned bb = cex(in[t ^ j2], in[(t ^ j2) ^ j1], km1);
    return cex(a, bb, (((t & j2) == 0) == asc));
}

// three consecutive stages (j1 > j2 > j3) fused: 8 reads, 7 cex.
// All predicate bits (k, j1, j2, j3) are invariant under XOR by lower j's.
__device__ __forceinline__ unsigned stage_triple(const unsigned* in, int t, int k,
                                                 int j1, int j2, int j3)
{
    bool asc = ((t & k) == 0);
    bool km1 = (((t & j1) == 0) == asc);
    bool km2 = (((t & j2) == 0) == asc);
    bool km3 = (((t & j3) == 0) == asc);
    int t0 = t, t1 = t ^ j3, t2 = t ^ j2, t3 = (t ^ j2) ^ j3;
    unsigned a0 = cex(in[t0], in[t0 ^ j1], km1);
    unsigned a1 = cex(in[t1], in[t1 ^ j1], km1);
    unsigned a2 = cex(in[t2], in[t2 ^ j1], km1);
    unsigned a3 = cex(in[t3], in[t3 ^ j1], km1);
    unsigned b0 = cex(a0, a2, km2);
    unsigned b1 = cex(a1, a3, km2);
    return cex(b0, b1, km3);
}

// intra-warp bitonic merge on 32-bit keys: j = jstart..1 via shuffles
__device__ __forceinline__ unsigned warp_merge32(unsigned v, int t, int k, int jstart)
{
    bool dir = ((t & k) == 0);
    #pragma unroll
    for (int j = jstart; j > 0; j >>= 1) {
        unsigned o = __shfl_xor_sync(0xffffffffu, v, j);
        bool keep_min = (((t & j) == 0) == dir);
        unsigned mn = v < o ? v : o;
        unsigned mx = v < o ? o : v;
        v = keep_min ? mn : mx;
    }
    return v;
}

// -------------------------------------------------------------------------
// Kernel 1: one block per graph.
// Phase A (once): smem adjacency bitmask (atomicOr dedup) -> deg, K, CSR.
// Phase B (x5):  seg gather -> hash -> fused bitonic (7 SMEM sections) ->
//                flag-scan ranks -> run-length histogram; label update via
//                binary search (skipped on the last iteration).
// Dynamic SMEM (217088 B, opt-in):
//   [0      , 131072) : unsigned smask[32768]   adjacency bits
//   [131072 , 196608) : u16 s_ent[32768]        CSR entries (even-aligned runs)
//   [196608 , 200704) : int s_lab[1024]         labels
//   [200704 , 204800) : int s_cnt[1024]         histogram counts
//   [204800 , 208896) : unsigned s_keyA[1024]   sort ping buffer
//   [208896 , 212992) : unsigned s_keyB[1024]   sort pong buffer (also run-pos)
//   [212992 , 217088) : int s_scan[1024]        rank per sorted position
// -------------------------------------------------------------------------
extern "C" __global__ void __launch_bounds__(1024, 1)
wl_kernel(const int* __restrict__ esrc, const int* __restrict__ edst,
          const int* __restrict__ labels0, const float* __restrict__ hw, int E)
{
    extern __shared__ unsigned char s_raw[];
    unsigned*       smask  = (unsigned*)s_raw;                  // 128KB
    unsigned short* s_ent  = (unsigned short*)(s_raw + 131072); // 64KB
    int*            s_lab  = (int*)(s_raw + 196608);            // 4KB
    int*            s_cnt  = (int*)(s_raw + 200704);            // 4KB
    unsigned*       s_keyA = (unsigned*)(s_raw + 204800);       // 4KB
    unsigned*       s_keyB = (unsigned*)(s_raw + 208896);       // 4KB
    int*            s_scan = (int*)(s_raw + 212992);            // 4KB
    __shared__ int s_warp[32];

    const int t    = threadIdx.x;
    const int b    = blockIdx.x;
    const int lane = t & 31;
    const int wid  = t >> 5;
    const float w0 = hw[0], w1 = hw[1];

    // --- zero mask + counts ---
    #pragma unroll
    for (int w = 0; w < NWORDS; w++) smask[t + w * 1024] = 0u;
    s_cnt[t] = 0;
    __syncthreads();

    // --- build directed adjacency bitmask (atomicOr dedupes edges) ---
    if ((E & 3) == 0) {
        const int4* s4 = (const int4*)(esrc + (size_t)b * E);
        const int4* d4 = (const int4*)(edst + (size_t)b * E);
        const int n4 = E >> 2;
        for (int i = t; i < n4; i += 1024) {
            int4 s = s4[i];
            int4 d = d4[i];
            atomicOr(&smask[(s.x << 5) + (d.x >> 5)], 1u << (d.x & 31));
            atomicOr(&smask[(s.y << 5) + (d.y >> 5)], 1u << (d.y & 31));
            atomicOr(&smask[(s.z << 5) + (d.z >> 5)], 1u << (d.z & 31));
            atomicOr(&smask[(s.w << 5) + (d.w >> 5)], 1u << (d.w & 31));
        }
    } else {
        for (int e = t; e < E; e += 1024) {
            int s = esrc[b * E + e];
            int d = edst[b * E + e];
            atomicOr(&smask[(s << 5) + (d >> 5)], 1u << (d & 31));
        }
    }

    // --- initial labels + histogram stage 0 ---
    int mylab = labels0[b * NN + t];
    s_lab[t] = mylab;
    atomicAdd(&s_cnt[mylab], 1);
    __syncthreads();

    // --- degree (staggered word order -> conflict-free LDS) ---
    int deg = 0;
    #pragma unroll
    for (int wi = 0; wi < NWORDS; wi++) {
        int w = (wi + t) & 31;
        deg += __popc(smask[(t << 5) + w]);
    }
    const int degPad = (deg + 1) & ~1;     // even-align each node's CSR run

    // --- K = max degree, exclusive scan of degPad -> even CSR offsets ---
    int kv = deg;
    #pragma unroll
    for (int o = 16; o > 0; o >>= 1) kv = max(kv, __shfl_xor_sync(0xffffffffu, kv, o));
    int incl = degPad;
    #pragma unroll
    for (int o = 1; o < 32; o <<= 1) {
        int n = __shfl_up_sync(0xffffffffu, incl, o);
        if (lane >= o) incl += n;
    }
    if (lane == 31) { s_warp[wid] = incl; s_scan[wid] = kv; }
    __syncthreads();
    if (t < 32) {
        int x = s_warp[t];
        #pragma unroll
        for (int o = 1; o < 32; o <<= 1) {
            int n = __shfl_up_sync(0xffffffffu, x, o);
            if (t >= o) x += n;
        }
        s_warp[t] = x;
        int m = s_scan[t];
        #pragma unroll
        for (int o = 16; o > 0; o >>= 1) m = max(m, __shfl_xor_sync(0xffffffffu, m, o));
        if (t == 0) s_scan[0] = m;
    }
    __syncthreads();
    const int K   = s_scan[0];
    const int off = (wid > 0 ? s_warp[wid - 1] : 0) + incl - degPad;  // even
    __syncthreads();

    // --- build CSR u16 neighbor entries (once) ---
    {
        int p = off;
        #pragma unroll
        for (int w = 0; w < NWORDS; w++) {
            unsigned m = smask[(t << 5) + w];
            int base = w << 5;
            while (m) {
                int bb = __ffs(m) - 1;
                m &= m - 1;
                s_ent[p++] = (unsigned short)(base + bb);
            }
        }
    }
    __syncthreads();

    const float Kw0 = __fmul_rn((float)K, w0);
    const unsigned* e32base = (const unsigned*)s_ent;

    for (int it = 0; it < NITER; it++) {
        // --- seg = sum of neighbor labels; u32-packed reads ---
        int seg = 0;
        {
            const unsigned* e32 = e32base + (off >> 1);
            const int nf = deg >> 1;
            #pragma unroll 4
            for (int n = 0; n < nf; n++) {
                unsigned e = e32[n];
                seg += s_lab[e & 0xFFFFu] + s_lab[e >> 16];
            }
            if (deg & 1) seg += s_lab[s_ent[off + deg - 1]];
        }

        // --- hashed = (K*w0)*lab + w1*(seg+deg-K), no FMA contraction ---
        float h = __fadd_rn(__fmul_rn(Kw0, (float)mylab),
                            __fmul_rn(w1, (float)(seg + deg - K)));
        h = __fadd_rn(h, 0.0f);               // canonicalize -0 -> +0
        unsigned u = __float_as_uint(h);
        u = (u & 0x80000000u) ? ~u : (u | 0x80000000u);   // order-preserving map
        const unsigned mykey = u;
        unsigned v = u;

        // --- warp phase: k = 2..32 in registers ---
        #pragma unroll
        for (int k = 2; k <= 32; k <<= 1)
            v = warp_merge32(v, t, k, k >> 1);

        unsigned* cur = s_keyA;
        unsigned* nxt = s_keyB;
        cur[t] = v;
        __syncthreads();

        // --- 7 SMEM sections (double-buffered, fused warp tails) ---
        // k=64: (32) + tail
        v = stage_single(cur, t, 64, 32);
        v = warp_merge32(v, t, 64, 16);
        nxt[t] = v; { unsigned* tmp = cur; cur = nxt; nxt = tmp; }
        __syncthreads();

        // k=128: (64,32) + tail
        v = stage_pair(cur, t, 128, 64, 32);
        v = warp_merge32(v, t, 128, 16);
        nxt[t] = v; { unsigned* tmp = cur; cur = nxt; nxt = tmp; }
        __syncthreads();

        // k=256: (128,64,32) + tail
        v = stage_triple(cur, t, 256, 128, 64, 32);
        v = warp_merge32(v, t, 256, 16);
        nxt[t] = v; { unsigned* tmp = cur; cur = nxt; nxt = tmp; }
        __syncthreads();

        // k=512: (256,128,64)
        v = stage_triple(cur, t, 512, 256, 128, 64);
        nxt[t] = v; { unsigned* tmp = cur; cur = nxt; nxt = tmp; }
        __syncthreads();
        // k=512: (32) + tail
        v = stage_single(cur, t, 512, 32);
        v = warp_merge32(v, t, 512, 16);
        nxt[t] = v; { unsigned* tmp = cur; cur = nxt; nxt = tmp; }
        __syncthreads();

        // k=1024: (512,256,128)
        v = stage_triple(cur, t, 1024, 512, 256, 128);
        nxt[t] = v; { unsigned* tmp = cur; cur = nxt; nxt = tmp; }
        __syncthreads();
        // k=1024: (64,32) + tail
        v = stage_pair(cur, t, 1024, 64, 32);
        v = warp_merge32(v, t, 1024, 16);
        nxt[t] = v; { unsigned* tmp = cur; cur = nxt; nxt = tmp; }
        __syncthreads();
        // cur[] fully sorted; nxt[] free; v = cur[t]

        // --- rank per sorted position: boundary flag + block scan ---
        int flag = 0;
        if (t > 0) flag = (v != cur[t - 1]) ? 1 : 0;
        int val = flag;
        #pragma unroll
        for (int o = 1; o < 32; o <<= 1) {
            int n = __shfl_up_sync(0xffffffffu, val, o);
            if (lane >= o) val += n;
        }
        if (lane == 31) s_warp[wid] = val;
        __syncthreads();
        if (t < 32) {
            int x = s_warp[t];
            #pragma unroll
            for (int o = 1; o < 32; o <<= 1) {
                int n = __shfl_up_sync(0xffffffffu, x, o);
                if (t >= o) x += n;
            }
            s_warp[t] = x;
        }
        __syncthreads();
        const int rank_p = val + (wid > 0 ? s_warp[wid - 1] : 0);
        int* s_pos = (int*)nxt;           // reuse free pong buffer
        s_scan[t] = rank_p;
        s_pos[t]  = 1024;                 // sentinel
        __syncthreads();

        const bool isstart = (t == 0) | (flag != 0);
        if (isstart) s_pos[rank_p] = t;
        __syncthreads();

        // --- atomic-free histogram: run-length = next start - my start ---
        if (isstart) {
            int end = (rank_p == 1023) ? 1024 : s_pos[rank_p + 1];
            s_cnt[rank_p] += end - t;
        }

        // --- label update (not needed after the last iteration) ---
        if (it < NITER - 1) {
            int lo = 0;
            #pragma unroll
            for (int s = 512; s > 0; s >>= 1)
                if (cur[lo + s - 1] < mykey) lo += s;
            int rank = s_scan[lo];
            s_lab[t] = rank;
            mylab    = rank;
        }
        __syncthreads();
    }

    // --- feats + norm ---
    float c = (float)s_cnt[t];
    g_feats[b * NN + t] = c;

    float sq = c * c;
    #pragma unroll
    for (int o = 16; o > 0; o >>= 1) sq += __shfl_xor_sync(0xffffffffu, sq, o);
    if (lane == 0) s_warp[wid] = __float_as_int(sq);
    __syncthreads();
    if (t < 32) {
        float x = __int_as_float(s_warp[t]);
        #pragma unroll
        for (int o = 16; o > 0; o >>= 1) x += __shfl_xor_sync(0xffffffffu, x, o);
        if (t == 0) g_dnorm[b] = sqrtf(x);
    }
}

// -------------------------------------------------------------------------
// Kernel 2: normalized Gram (measured-best shape). Grid (64, 2) x 1024:
// warp w of block (b, jt) computes out[b][jt*32+w].
// -------------------------------------------------------------------------
extern "C" __global__ void __launch_bounds__(1024)
gram_kernel(float* __restrict__ out)
{
    __shared__ float sf[NN];
    const int b  = blockIdx.x;
    const int jt = blockIdx.y;
    const int t  = threadIdx.x;
    sf[t] = g_feats[b * NN + t];
    __syncthreads();

    const int warp = t >> 5, lane = t & 31;
    const int j = jt * 32 + warp;
    const float4* sf4 = (const float4*)sf;
    const float4* fj4 = (const float4*)&g_feats[j * NN];
    float s = 0.0f;
    #pragma unroll
    for (int k = lane; k < NN / 4; k += 32) {
        float4 a = sf4[k];
        float4 c = fj4[k];
        s += a.x * c.x + a.y * c.y + a.z * c.z + a.w * c.w;
    }
    #pragma unroll
    for (int o = 16; o > 0; o >>= 1) s += __shfl_xor_sync(0xffffffffu, s, o);
    if (lane == 0) out[b * NB + j] = s / (g_dnorm[b] * g_dnorm[j]);
}

extern "C" void kernel_launch(void* const* d_in, const int* in_sizes, int n_in,
                              void* d_out, int out_size)
{
    const int*   esrc = (const int*)d_in[0];
    const int*   edst = (const int*)d_in[1];
    const int*   lab  = (const int*)d_in[2];
    const float* hw   = (const float*)d_in[3];
    const int E = in_sizes[0] / NB;

    const size_t smem_wl = 217088;  // 128K mask + 64K ent + 5x4K arrays
    static bool attr_done = false;
    if (!attr_done) {
        cudaFuncSetAttribute(wl_kernel, cudaFuncAttributeMaxDynamicSharedMemorySize,
                             (int)smem_wl);
        attr_done = true;
    }
    wl_kernel<<<NB, 1024, smem_wl>>>(esrc, edst, lab, hw, E);
    gram_kernel<<<dim3(NB, 2), 1024>>>((float*)d_out);
}

// round 9
// speedup vs baseline: 1.1051x; 1.0416x over previous
#include <cuda_runtime.h>

#define NB 64
#define NN 1024
#define NWORDS 32          // NN/32 bitmask words per node row
#define NITER 5

// scratch (no allocations allowed)
__device__ float g_feats[NB * NN];   // per-graph label histograms (6 stages)
__device__ float g_dnorm[NB];        // sqrt(dot(feats_b, feats_b))

// compare-exchange
__device__ __forceinline__ unsigned cex(unsigned a, unsigned b, bool keep_min)
{
    unsigned mn = a < b ? a : b;
    unsigned mx = a < b ? b : a;
    return keep_min ? mn : mx;
}

__device__ __forceinline__ unsigned stage_single(const unsigned* in, int t, int k, int j)
{
    bool asc = ((t & k) == 0);
    return cex(in[t], in[t ^ j], (((t & j) == 0) == asc));
}

// two consecutive stages (j1 then j2=j1/2) fused: 4 reads, 3 cex.
__device__ __forceinline__ unsigned stage_pair(const unsigned* in, int t, int k, int j1, int j2)
{
    bool asc = ((t & k) == 0);
    bool km1 = (((t & j1) == 0) == asc);
    unsigned a  = cex(in[t],      in[t ^ j1],        km1);
    unsigned bb = cex(in[t ^ j2], in[(t ^ j2) ^ j1], km1);
    return cex(a, bb, (((t & j2) == 0) == asc));
}

// intra-warp bitonic merge on 32-bit keys: j = jstart..1 via shuffles
__device__ __forceinline__ unsigned warp_merge32(unsigned v, int t, int k, int jstart)
{
    bool dir = ((t & k) == 0);
    #pragma unroll
    for (int j = jstart; j > 0; j >>= 1) {
        unsigned o = __shfl_xor_sync(0xffffffffu, v, j);
        bool keep_min = (((t & j) == 0) == dir);
        unsigned mn = v < o ? v : o;
        unsigned mx = v < o ? o : v;
        v = keep_min ? mn : mx;
    }
    return v;
}

// -------------------------------------------------------------------------
// Kernel 1: one block per graph.
// Dynamic SMEM (217088 B, opt-in):
//   [0      , 131072) : unsigned smask[32768]   adjacency bits
//   [131072 , 196608) : u16 s_ent[32768]        CSR entries (even-aligned runs)
//   [196608 , 200704) : int s_lab[1024]         labels
//   [200704 , 204800) : int s_cnt[1024]         histogram counts
//   [204800 , 208896) : unsigned s_keyA[1024]   sort ping buffer
//   [208896 , 212992) : unsigned s_keyB[1024]   sort pong buffer (also run-pos)
//   [212992 , 217088) : int s_scan[1024]        rank per sorted position
// -------------------------------------------------------------------------
extern "C" __global__ void __launch_bounds__(1024, 1)
wl_kernel(const int* __restrict__ esrc, const int* __restrict__ edst,
          const int* __restrict__ labels0, const float* __restrict__ hw, int E)
{
    extern __shared__ unsigned char s_raw[];
    unsigned*       smask  = (unsigned*)s_raw;                  // 128KB
    unsigned short* s_ent  = (unsigned short*)(s_raw + 131072); // 64KB
    int*            s_lab  = (int*)(s_raw + 196608);            // 4KB
    int*            s_cnt  = (int*)(s_raw + 200704);            // 4KB
    unsigned*       s_keyA = (unsigned*)(s_raw + 204800);       // 4KB
    unsigned*       s_keyB = (unsigned*)(s_raw + 208896);       // 4KB
    int*            s_scan = (int*)(s_raw + 212992);            // 4KB
    __shared__ int s_warp[32];

    const int t    = threadIdx.x;
    const int b    = blockIdx.x;
    const int lane = t & 31;
    const int wid  = t >> 5;
    const float w0 = hw[0], w1 = hw[1];

    // --- zero mask + counts ---
    #pragma unroll
    for (int w = 0; w < NWORDS; w++) smask[t + w * 1024] = 0u;
    s_cnt[t] = 0;
    __syncthreads();

    // --- build directed adjacency bitmask (atomicOr dedupes edges) ---
    if ((E & 3) == 0) {
        const int4* s4 = (const int4*)(esrc + (size_t)b * E);
        const int4* d4 = (const int4*)(edst + (size_t)b * E);
        const int n4 = E >> 2;
        for (int i = t; i < n4; i += 1024) {
            int4 s = s4[i];
            int4 d = d4[i];
            atomicOr(&smask[(s.x << 5) + (d.x >> 5)], 1u << (d.x & 31));
            atomicOr(&smask[(s.y << 5) + (d.y >> 5)], 1u << (d.y & 31));
            atomicOr(&smask[(s.z << 5) + (d.z >> 5)], 1u << (d.z & 31));
            atomicOr(&smask[(s.w << 5) + (d.w >> 5)], 1u << (d.w & 31));
        }
    } else {
        for (int e = t; e < E; e += 1024) {
            int s = esrc[b * E + e];
            int d = edst[b * E + e];
            atomicOr(&smask[(s << 5) + (d >> 5)], 1u << (d & 31));
        }
    }

    // --- initial labels + histogram stage 0 ---
    int mylab = labels0[b * NN + t];
    s_lab[t] = mylab;
    atomicAdd(&s_cnt[mylab], 1);
    __syncthreads();

    // --- degree (staggered word order -> conflict-free LDS) ---
    int deg = 0;
    #pragma unroll
    for (int wi = 0; wi < NWORDS; wi++) {
        int w = (wi + t) & 31;
        deg += __popc(smask[(t << 5) + w]);
    }
    const int degPad = (deg + 1) & ~1;     // even-align each node's CSR run

    // --- K = max degree, exclusive scan of degPad -> even CSR offsets ---
    int kv = deg;
    #pragma unroll
    for (int o = 16; o > 0; o >>= 1) kv = max(kv, __shfl_xor_sync(0xffffffffu, kv, o));
    int incl = degPad;
    #pragma unroll
    for (int o = 1; o < 32; o <<= 1) {
        int n = __shfl_up_sync(0xffffffffu, incl, o);
        if (lane >= o) incl += n;
    }
    if (lane == 31) { s_warp[wid] = incl; s_scan[wid] = kv; }
    __syncthreads();
    if (t < 32) {
        int x = s_warp[t];
        #pragma unroll
        for (int o = 1; o < 32; o <<= 1) {
            int n = __shfl_up_sync(0xffffffffu, x, o);
            if (t >= o) x += n;
        }
        s_warp[t] = x;
        int m = s_scan[t];
        #pragma unroll
        for (int o = 16; o > 0; o >>= 1) m = max(m, __shfl_xor_sync(0xffffffffu, m, o));
        if (t == 0) s_scan[0] = m;
    }
    __syncthreads();
    const int K   = s_scan[0];
    const int off = (wid > 0 ? s_warp[wid - 1] : 0) + incl - degPad;  // even
    __syncthreads();

    // --- build CSR u16 neighbor entries (once) ---
    {
        int p = off;
        #pragma unroll
        for (int w = 0; w < NWORDS; w++) {
            unsigned m = smask[(t << 5) + w];
            int base = w << 5;
            while (m) {
                int bb = __ffs(m) - 1;
                m &= m - 1;
                s_ent[p++] = (unsigned short)(base + bb);
            }
        }
    }
    __syncthreads();

    const float Kw0 = __fmul_rn((float)K, w0);
    const unsigned* e32base = (const unsigned*)s_ent;

    for (int it = 0; it < NITER; it++) {
        // --- seg = sum of neighbor labels; u32-packed reads ---
        int seg = 0;
        {
            const unsigned* e32 = e32base + (off >> 1);
            const int nf = deg >> 1;
            #pragma unroll 4
            for (int n = 0; n < nf; n++) {
                unsigned e = e32[n];
                seg += s_lab[e & 0xFFFFu] + s_lab[e >> 16];
            }
            if (deg & 1) seg += s_lab[s_ent[off + deg - 1]];
        }

        // --- hashed = (K*w0)*lab + w1*(seg+deg-K), no FMA contraction ---
        float h = __fadd_rn(__fmul_rn(Kw0, (float)mylab),
                            __fmul_rn(w1, (float)(seg + deg - K)));
        h = __fadd_rn(h, 0.0f);               // canonicalize -0 -> +0
        unsigned u = __float_as_uint(h);
        u = (u & 0x80000000u) ? ~u : (u | 0x80000000u);   // order-preserving map
        const unsigned mykey = u;
        unsigned v = u;

        // --- warp phase: k = 2..32 in registers ---
        #pragma unroll
        for (int k = 2; k <= 32; k <<= 1)
            v = warp_merge32(v, t, k, k >> 1);

        unsigned* cur = s_keyA;
        unsigned* nxt = s_keyB;
        cur[t] = v;
        __syncthreads();

        // --- k=64 ---
        v = stage_single(cur, t, 64, 32);
        v = warp_merge32(v, t, 64, 16);
        nxt[t] = v; { unsigned* tmp = cur; cur = nxt; nxt = tmp; }
        __syncthreads();

        // --- k=128 ---
        v = stage_pair(cur, t, 128, 64, 32);
        v = warp_merge32(v, t, 128, 16);
        nxt[t] = v; { unsigned* tmp = cur; cur = nxt; nxt = tmp; }
        __syncthreads();

        // --- k=256 ---
        v = stage_pair(cur, t, 256, 128, 64);
        nxt[t] = v; { unsigned* tmp = cur; cur = nxt; nxt = tmp; }
        __syncthreads();
        v = stage_single(cur, t, 256, 32);
        v = warp_merge32(v, t, 256, 16);
        nxt[t] = v; { unsigned* tmp = cur; cur = nxt; nxt = tmp; }
        __syncthreads();

        // --- k=512 ---
        v = stage_pair(cur, t, 512, 256, 128);
        nxt[t] = v; { unsigned* tmp = cur; cur = nxt; nxt = tmp; }
        __syncthreads();
        v = stage_pair(cur, t, 512, 64, 32);
        v = warp_merge32(v, t, 512, 16);
        nxt[t] = v; { unsigned* tmp = cur; cur = nxt; nxt = tmp; }
        __syncthreads();

        // --- k=1024 ---
        v = stage_pair(cur, t, 1024, 512, 256);
        nxt[t] = v; { unsigned* tmp = cur; cur = nxt; nxt = tmp; }
        __syncthreads();
        v = stage_pair(cur, t, 1024, 128, 64);
        nxt[t] = v; { unsigned* tmp = cur; cur = nxt; nxt = tmp; }
        __syncthreads();
        v = stage_single(cur, t, 1024, 32);
        v = warp_merge32(v, t, 1024, 16);
        nxt[t] = v; { unsigned* tmp = cur; cur = nxt; nxt = tmp; }
        __syncthreads();
        // cur[] fully sorted; nxt[] free; v = cur[t]

        // --- rank per sorted position: boundary flag + block scan ---
        int flag = 0;
        if (t > 0) flag = (v != cur[t - 1]) ? 1 : 0;
        int val = flag;
        #pragma unroll
        for (int o = 1; o < 32; o <<= 1) {
            int n = __shfl_up_sync(0xffffffffu, val, o);
            if (lane >= o) val += n;
        }
        if (lane == 31) s_warp[wid] = val;
        __syncthreads();
        if (t < 32) {
            int x = s_warp[t];
            #pragma unroll
            for (int o = 1; o < 32; o <<= 1) {
                int n = __shfl_up_sync(0xffffffffu, x, o);
                if (t >= o) x += n;
            }
            s_warp[t] = x;
        }
        __syncthreads();
        const int rank_p = val + (wid > 0 ? s_warp[wid - 1] : 0);
        int* s_pos = (int*)nxt;           // reuse free pong buffer
        s_scan[t] = rank_p;
        s_pos[t]  = 1024;                 // sentinel
        __syncthreads();

        const bool isstart = (t == 0) | (flag != 0);
        if (isstart) s_pos[rank_p] = t;
        __syncthreads();

        // --- atomic-free histogram: run-length = next start - my start ---
        if (isstart) {
            int end = (rank_p == 1023) ? 1024 : s_pos[rank_p + 1];
            s_cnt[rank_p] += end - t;
        }

        // --- label update via binary search (skip after last iteration) ---
        if (it < NITER - 1) {
            int lo = 0;
            #pragma unroll
            for (int s = 512; s > 0; s >>= 1)
                if (cur[lo + s - 1] < mykey) lo += s;
            int rank = s_scan[lo];
            s_lab[t] = rank;
            mylab    = rank;
        }
        __syncthreads();
    }

    // --- feats + norm ---
    float c = (float)s_cnt[t];
    g_feats[b * NN + t] = c;

    float sq = c * c;
    #pragma unroll
    for (int o = 16; o > 0; o >>= 1) sq += __shfl_xor_sync(0xffffffffu, sq, o);
    if (lane == 0) s_warp[wid] = __float_as_int(sq);
    __syncthreads();
    if (t < 32) {
        float x = __int_as_float(s_warp[t]);
        #pragma unroll
        for (int o = 16; o > 0; o >>= 1) x += __shfl_xor_sync(0xffffffffu, x, o);
        if (t == 0) g_dnorm[b] = sqrtf(x);
    }
}

// -------------------------------------------------------------------------
// Kernel 2: normalized Gram (measured-best shape). Grid (64, 2) x 1024:
// warp w of block (b, jt) computes out[b][jt*32+w].
// -------------------------------------------------------------------------
extern "C" __global__ void __launch_bounds__(1024)
gram_kernel(float* __restrict__ out)
{
    __shared__ float sf[NN];
    const int b  = blockIdx.x;
    const int jt = blockIdx.y;
    const int t  = threadIdx.x;
    sf[t] = g_feats[b * NN + t];
    __syncthreads();

    const int warp = t >> 5, lane = t & 31;
    const int j = jt * 32 + warp;
    const float4* sf4 = (const float4*)sf;
    const float4* fj4 = (const float4*)&g_feats[j * NN];
    float s = 0.0f;
    #pragma unroll
    for (int k = lane; k < NN / 4; k += 32) {
        float4 a = sf4[k];
        float4 c = fj4[k];
        s += a.x * c.x + a.y * c.y + a.z * c.z + a.w * c.w;
    }
    #pragma unroll
    for (int o = 16; o > 0; o >>= 1) s += __shfl_xor_sync(0xffffffffu, s, o);
    if (lane == 0) out[b * NB + j] = s / (g_dnorm[b] * g_dnorm[j]);
}

// -------------------------------------------------------------------------
// Dummy kernel: no-op. Three of these pad the launch period to 5 so that
// ncu's "-s 5 -c 1" capture lands on wl_kernel (launch index 5) instead of
// always sampling gram_kernel. Negligible runtime (~sub-us each).
// -------------------------------------------------------------------------
extern "C" __global__ void dummy_kernel() {}

extern "C" void kernel_launch(void* const* d_in, const int* in_sizes, int n_in,
                              void* d_out, int out_size)
{
    const int*   esrc = (const int*)d_in[0];
    const int*   edst = (const int*)d_in[1];
    const int*   lab  = (const int*)d_in[2];
    const float* hw   = (const float*)d_in[3];
    const int E = in_sizes[0] / NB;

    const size_t smem_wl = 217088;  // 128K mask + 64K ent + 5x4K arrays
    static bool attr_done = false;
    if (!attr_done) {
        cudaFuncSetAttribute(wl_kernel, cudaFuncAttributeMaxDynamicSharedMemorySize,
                             (int)smem_wl);
        attr_done = true;
    }
    wl_kernel<<<NB, 1024, smem_wl>>>(esrc, edst, lab, hw, E);
    gram_kernel<<<dim3(NB, 2), 1024>>>((float*)d_out);
    dummy_kernel<<<1, 32>>>();
    dummy_kernel<<<1, 32>>>();
    dummy_kernel<<<1, 32>>>();
}

// round 12
// speedup vs baseline: 1.1448x; 1.0359x over previous
#include <cuda_runtime.h>

#define NB 64
#define NN 1024
#define NWORDS 32          // NN/32 bitmask words per node row
#define NITER 5

// scratch (no allocations allowed)
__device__ float g_feats[NB * NN];   // per-graph label histograms (6 stages)
__device__ float g_dnorm[NB];        // sqrt(dot(feats_b, feats_b))

// compare-exchange
__device__ __forceinline__ unsigned cex(unsigned a, unsigned b, bool keep_min)
{
    unsigned mn = a < b ? a : b;
    unsigned mx = a < b ? b : a;
    return keep_min ? mn : mx;
}

__device__ __forceinline__ unsigned stage_single(const unsigned* in, int t, int k, int j)
{
    bool asc = ((t & k) == 0);
    return cex(in[t], in[t ^ j], (((t & j) == 0) == asc));
}

// two consecutive stages (j1 then j2=j1/2) fused: 4 reads, 3 cex.
__device__ __forceinline__ unsigned stage_pair(const unsigned* in, int t, int k, int j1, int j2)
{
    bool asc = ((t & k) == 0);
    bool km1 = (((t & j1) == 0) == asc);
    unsigned a  = cex(in[t],      in[t ^ j1],        km1);
    unsigned bb = cex(in[t ^ j2], in[(t ^ j2) ^ j1], km1);
    return cex(a, bb, (((t & j2) == 0) == asc));
}

// intra-warp bitonic merge on 32-bit keys: j = jstart..1 via shuffles
__device__ __forceinline__ unsigned warp_merge32(unsigned v, int t, int k, int jstart)
{
    bool dir = ((t & k) == 0);
    #pragma unroll
    for (int j = jstart; j > 0; j >>= 1) {
        unsigned o = __shfl_xor_sync(0xffffffffu, v, j);
        bool keep_min = (((t & j) == 0) == dir);
        unsigned mn = v < o ? v : o;
        unsigned mx = v < o ? o : v;
        v = keep_min ? mn : mx;
    }
    return v;
}

// -------------------------------------------------------------------------
// Kernel 1: one block per graph.
// Dynamic SMEM (217088 B, opt-in):
//   [0      , 131072) : unsigned smask[32768]   adjacency bits
//   [131072 , 196608) : u16 s_ent[32768]        CSR entries (even-aligned runs)
//   [196608 , 200704) : int s_lab[1024]         labels
//   [200704 , 204800) : int s_cnt[1024]         histogram counts
//   [204800 , 208896) : unsigned s_keyA[1024]   sort ping buffer
//   [208896 , 212992) : unsigned s_keyB[1024]   sort pong buffer (also run-pos)
//   [212992 , 217088) : int s_scan[1024]        rank per sorted position
// -------------------------------------------------------------------------
extern "C" __global__ void __launch_bounds__(1024, 1)
wl_kernel(const int* __restrict__ esrc, const int* __restrict__ edst,
          const int* __restrict__ labels0, const float* __restrict__ hw, int E)
{
    extern __shared__ unsigned char s_raw[];
    unsigned*       smask  = (unsigned*)s_raw;                  // 128KB
    unsigned short* s_ent  = (unsigned short*)(s_raw + 131072); // 64KB
    int*            s_lab  = (int*)(s_raw + 196608);            // 4KB
    int*            s_cnt  = (int*)(s_raw + 200704);            // 4KB
    unsigned*       s_keyA = (unsigned*)(s_raw + 204800);       // 4KB
    unsigned*       s_keyB = (unsigned*)(s_raw + 208896);       // 4KB
    int*            s_scan = (int*)(s_raw + 212992);            // 4KB
    __shared__ int s_warp[32];

    const int t    = threadIdx.x;
    const int b    = blockIdx.x;
    const int lane = t & 31;
    const int wid  = t >> 5;
    const float w0 = hw[0], w1 = hw[1];

    // --- zero mask + counts ---
    #pragma unroll
    for (int w = 0; w < NWORDS; w++) smask[t + w * 1024] = 0u;
    s_cnt[t] = 0;
    __syncthreads();

    // --- build directed adjacency bitmask (atomicOr dedupes edges) ---
    if ((E & 3) == 0) {
        const int4* s4 = (const int4*)(esrc + (size_t)b * E);
        const int4* d4 = (const int4*)(edst + (size_t)b * E);
        const int n4 = E >> 2;
        for (int i = t; i < n4; i += 1024) {
            int4 s = s4[i];
            int4 d = d4[i];
            atomicOr(&smask[(s.x << 5) + (d.x >> 5)], 1u << (d.x & 31));
            atomicOr(&smask[(s.y << 5) + (d.y >> 5)], 1u << (d.y & 31));
            atomicOr(&smask[(s.z << 5) + (d.z >> 5)], 1u << (d.z & 31));
            atomicOr(&smask[(s.w << 5) + (d.w >> 5)], 1u << (d.w & 31));
        }
    } else {
        for (int e = t; e < E; e += 1024) {
            int s = esrc[b * E + e];
            int d = edst[b * E + e];
            atomicOr(&smask[(s << 5) + (d >> 5)], 1u << (d & 31));
        }
    }

    // --- initial labels + stage-0 histogram (warp-aggregated atomics) ---
    int mylab = labels0[b * NN + t];
    s_lab[t] = mylab;
    {
        unsigned peers = __match_any_sync(0xffffffffu, mylab);
        int leader = __ffs(peers) - 1;
        int cnt    = __popc(peers);
        if (lane == leader) atomicAdd(&s_cnt[mylab], cnt);
    }
    __syncthreads();

    // --- degree (staggered word order -> conflict-free LDS) ---
    int deg = 0;
    #pragma unroll
    for (int wi = 0; wi < NWORDS; wi++) {
        int w = (wi + t) & 31;
        deg += __popc(smask[(t << 5) + w]);
    }
    const int degPad = (deg + 1) & ~1;     // even-align each node's CSR run

    // --- K = max degree, exclusive scan of degPad -> even CSR offsets ---
    int kv = deg;
    #pragma unroll
    for (int o = 16; o > 0; o >>= 1) kv = max(kv, __shfl_xor_sync(0xffffffffu, kv, o));
    int incl = degPad;
    #pragma unroll
    for (int o = 1; o < 32; o <<= 1) {
        int n = __shfl_up_sync(0xffffffffu, incl, o);
        if (lane >= o) incl += n;
    }
    if (lane == 31) { s_warp[wid] = incl; s_scan[wid] = kv; }
    __syncthreads();
    int wpre, K;
    {
        int x = s_warp[lane];
        int xm = (lane < wid) ? x : 0;
        #pragma unroll
        for (int o = 16; o > 0; o >>= 1) xm += __shfl_xor_sync(0xffffffffu, xm, o);
        wpre = xm;
        int m = s_scan[lane & 31];
        #pragma unroll
        for (int o = 16; o > 0; o >>= 1) m = max(m, __shfl_xor_sync(0xffffffffu, m, o));
        K = m;
    }
    const int off = wpre + incl - degPad;  // even exclusive offset
    __syncthreads();

    // --- build CSR u16 neighbor entries (once) ---
    {
        int p = off;
        #pragma unroll
        for (int w = 0; w < NWORDS; w++) {
            unsigned m = smask[(t << 5) + w];
            int base = w << 5;
            while (m) {
                int bb = __ffs(m) - 1;
                m &= m - 1;
                s_ent[p++] = (unsigned short)(base + bb);
            }
        }
    }
    __syncthreads();

    const float Kw0 = __fmul_rn((float)K, w0);
    const unsigned* e32base = (const unsigned*)s_ent;

    for (int it = 0; it < NITER; it++) {
        // --- seg = sum of neighbor labels; u32-packed reads ---
        int seg = 0;
        {
            const unsigned* e32 = e32base + (off >> 1);
            const int nf = deg >> 1;
            #pragma unroll 4
            for (int n = 0; n < nf; n++) {
                unsigned e = e32[n];
                seg += s_lab[e & 0xFFFFu] + s_lab[e >> 16];
            }
            if (deg & 1) seg += s_lab[s_ent[off + deg - 1]];
        }

        // --- hashed = (K*w0)*lab + w1*(seg+deg-K), no FMA contraction ---
        float h = __fadd_rn(__fmul_rn(Kw0, (float)mylab),
                            __fmul_rn(w1, (float)(seg + deg - K)));
        h = __fadd_rn(h, 0.0f);               // canonicalize -0 -> +0
        unsigned u = __float_as_uint(h);
        u = (u & 0x80000000u) ? ~u : (u | 0x80000000u);   // order-preserving map
        const unsigned mykey = u;
        unsigned v = u;

        // --- warp phase: k = 2..32 in registers ---
        #pragma unroll
        for (int k = 2; k <= 32; k <<= 1)
            v = warp_merge32(v, t, k, k >> 1);

        unsigned* cur = s_keyA;
        unsigned* nxt = s_keyB;
        cur[t] = v;
        __syncthreads();

        // --- k=64 ---
        v = stage_single(cur, t, 64, 32);
        v = warp_merge32(v, t, 64, 16);
        nxt[t] = v; { unsigned* tmp = cur; cur = nxt; nxt = tmp; }
        __syncthreads();

        // --- k=128 ---
        v = stage_pair(cur, t, 128, 64, 32);
        v = warp_merge32(v, t, 128, 16);
        nxt[t] = v; { unsigned* tmp = cur; cur = nxt; nxt = tmp; }
        __syncthreads();

        // --- k=256 ---
        v = stage_pair(cur, t, 256, 128, 64);
        nxt[t] = v; { unsigned* tmp = cur; cur = nxt; nxt = tmp; }
        __syncthreads();
        v = stage_single(cur, t, 256, 32);
        v = warp_merge32(v, t, 256, 16);
        nxt[t] = v; { unsigned* tmp = cur; cur = nxt; nxt = tmp; }
        __syncthreads();

        // --- k=512 ---
        v = stage_pair(cur, t, 512, 256, 128);
        nxt[t] = v; { unsigned* tmp = cur; cur = nxt; nxt = tmp; }
        __syncthreads();
        v = stage_pair(cur, t, 512, 64, 32);
        v = warp_merge32(v, t, 512, 16);
        nxt[t] = v; { unsigned* tmp = cur; cur = nxt; nxt = tmp; }
        __syncthreads();

        // --- k=1024 ---
        v = stage_pair(cur, t, 1024, 512, 256);
        nxt[t] = v; { unsigned* tmp = cur; cur = nxt; nxt = tmp; }
        __syncthreads();
        v = stage_pair(cur, t, 1024, 128, 64);
        nxt[t] = v; { unsigned* tmp = cur; cur = nxt; nxt = tmp; }
        __syncthreads();
        v = stage_single(cur, t, 1024, 32);
        v = warp_merge32(v, t, 1024, 16);
        nxt[t] = v; { unsigned* tmp = cur; cur = nxt; nxt = tmp; }
        __syncthreads();
        // cur[] fully sorted; nxt[] holds stale keys (reused as s_pos); v = cur[t]

        // --- tail section 1: flags, warp scan, broadcast prefix, scatter ---
        // No sentinel init needed: s_pos[r] is written for EVERY rank r in
        // [0, R] by exactly one run-start thread; the final run's end is
        // detected via rank_p == R (R = s_scan[1023], read after barrier).
        int flag = 0;
        if (t > 0) flag = (v != cur[t - 1]) ? 1 : 0;
        int val = flag;
        #pragma unroll
        for (int o = 1; o < 32; o <<= 1) {
            int n = __shfl_up_sync(0xffffffffu, val, o);
            if (lane >= o) val += n;
        }
        if (lane == 31) s_warp[wid] = val;
        __syncthreads();

        // cross-warp prefix without a second barrier: broadcast-read + reduce
        int wp = s_warp[lane];
        wp = (lane < wid) ? wp : 0;
        #pragma unroll
        for (int o = 16; o > 0; o >>= 1) wp += __shfl_xor_sync(0xffffffffu, wp, o);
        const int rank_p = val + wp;
        int* s_pos = (int*)nxt;
        s_scan[t] = rank_p;
        const bool isstart = (t == 0) | (flag != 0);
        if (isstart) s_pos[rank_p] = t;
        __syncthreads();

        // --- tail section 2: run-length histogram + label update ---
        if (isstart) {
            const int R = s_scan[1023];          // max rank this iteration
            int end = (rank_p == R) ? 1024 : s_pos[rank_p + 1];
            s_cnt[rank_p] += end - t;
        }
        if (it < NITER - 1) {
            int lo = 0;
            #pragma unroll
            for (int s = 512; s > 0; s >>= 1)
                if (cur[lo + s - 1] < mykey) lo += s;
            int rank = s_scan[lo];
            s_lab[t] = rank;
            mylab    = rank;
        }
        __syncthreads();
    }

    // --- feats + norm ---
    float c = (float)s_cnt[t];
    g_feats[b * NN + t] = c;

    float sq = c * c;
    #pragma unroll
    for (int o = 16; o > 0; o >>= 1) sq += __shfl_xor_sync(0xffffffffu, sq, o);
    if (lane == 0) s_warp[wid] = __float_as_int(sq);
    __syncthreads();
    if (t < 32) {
        float x = __int_as_float(s_warp[t]);
        #pragma unroll
        for (int o = 16; o > 0; o >>= 1) x += __shfl_xor_sync(0xffffffffu, x, o);
        if (t == 0) g_dnorm[b] = sqrtf(x);
    }
}

// -------------------------------------------------------------------------
// Kernel 2: normalized Gram. Grid (64, 4) x 512: warp w of block (b, jt)
// computes out[b][jt*16+w] (one 1024-dot per warp). 256 blocks.
// -------------------------------------------------------------------------
extern "C" __global__ void __launch_bounds__(512)
gram_kernel(float* __restrict__ out)
{
    __shared__ float sf[NN];
    const int b  = blockIdx.x;
    const int jt = blockIdx.y;
    const int t  = threadIdx.x;
    sf[t]       = g_feats[b * NN + t];
    sf[t + 512] = g_feats[b * NN + t + 512];
    __syncthreads();

    const int warp = t >> 5, lane = t & 31;
    const int j = jt * 16 + warp;
    const float4* sf4 = (const float4*)sf;
    const float4* fj4 = (const float4*)&g_feats[j * NN];
    float s = 0.0f;
    #pragma unroll
    for (int k = lane; k < NN / 4; k += 32) {
        float4 a = sf4[k];
        float4 c = fj4[k];
        s += a.x * c.x + a.y * c.y + a.z * c.z + a.w * c.w;
    }
    #pragma unroll
    for (int o = 16; o > 0; o >>= 1) s += __shfl_xor_sync(0xffffffffu, s, o);
    if (lane == 0) out[b * NB + j] = s / (g_dnorm[b] * g_dnorm[j]);
}

extern "C" void kernel_launch(void* const* d_in, const int* in_sizes, int n_in,
                              void* d_out, int out_size)
{
    const int*   esrc = (const int*)d_in[0];
    const int*   edst = (const int*)d_in[1];
    const int*   lab  = (const int*)d_in[2];
    const float* hw   = (const float*)d_in[3];
    const int E = in_sizes[0] / NB;

    const size_t smem_wl = 217088;  // 128K mask + 64K ent + 5x4K arrays
    static bool attr_done = false;
    if (!attr_done) {
        cudaFuncSetAttribute(wl_kernel, cudaFuncAttributeMaxDynamicSharedMemorySize,
                             (int)smem_wl);
        attr_done = true;
    }
    wl_kernel<<<NB, 1024, smem_wl>>>(esrc, edst, lab, hw, E);
    gram_kernel<<<dim3(NB, 4), 512>>>((float*)d_out);
}